// round 16
// baseline (speedup 1.0000x reference)
#include <cuda_runtime.h>
#include <cuda_bf16.h>
#include <math.h>
#include <stdint.h>

#define NN  10000   // nodes
#define NE  50000   // edges
#define HD  64      // hidden
#define BG  256     // batch graphs
#define NEF 4
#define NNF 11
#define NTG 12      // targets
#define IC  128     // 2H
#define KZ  4160    // 64*65 : Zcat columns (64i x 64k + 64 hsum)

// ---------------- scratch (static device globals; no allocation) ----------------
__device__ float g_e1[NE * HD];
__device__ __nv_bfloat16 g_zh[(size_t)NN * KZ];        // 83 MB (Z hi)
__device__ __nv_bfloat16 g_zl[(size_t)NN * KZ];        // 83 MB (Z lo)
__device__ __nv_bfloat16 g_vh[HD * KZ];
__device__ __nv_bfloat16 g_vl[HD * KZ];
__device__ float g_h[NN * HD];
__device__ float g_m[NN * HD];
__device__ float g_hx[NN * (HD + NNF)];
__device__ float g_h2[NN * IC];
__device__ float g_eatt[NN];
__device__ float g_qstar[BG * 2 * IC];
__device__ float g_h0[BG * IC];
__device__ float g_c0[BG * IC];
__device__ float g_h1[BG * IC];
__device__ float g_c1[BG * IC];
__device__ float g_wcat0T[384 * 512];   // transposed [K][512]
__device__ float g_wcat1T[256 * 512];
__device__ float g_bs0[512];
__device__ float g_bs1[512];
__device__ float g_t2a[BG * 512];
__device__ int   g_gs[BG];
__device__ int   g_ge[BG];
// edge sort-by-dst
__device__ int   g_cnt[NN];
__device__ int   g_cur[NN];
__device__ int   g_offs[NN + 1];
__device__ int   g_eord[NE];

#define ID_E1     0
#define ID_H      1
#define ID_M      2
#define ID_HX     3
#define ID_H2     4
#define ID_QSTAR  5
#define ID_T2A    6
#define N_IDS     7

__device__ float* g_table[N_IDS];

__device__ __forceinline__ float sigf(float x) { return 1.0f / (1.0f + expf(-x)); }

// ---------------- bf16 mma / ldmatrix / cp.async helpers ----------------
__device__ __forceinline__ void mma_bf16(float* d, const unsigned* a, const unsigned* b) {
    asm volatile(
        "mma.sync.aligned.m16n8k16.row.col.f32.bf16.bf16.f32 "
        "{%0,%1,%2,%3}, {%4,%5,%6,%7}, {%8,%9}, {%0,%1,%2,%3};\n"
        : "+f"(d[0]), "+f"(d[1]), "+f"(d[2]), "+f"(d[3])
        : "r"(a[0]), "r"(a[1]), "r"(a[2]), "r"(a[3]), "r"(b[0]), "r"(b[1]));
}

__device__ __forceinline__ void ldsm4(unsigned* r, uint32_t addr) {
    asm volatile("ldmatrix.sync.aligned.m8n8.x4.shared.b16 {%0,%1,%2,%3}, [%4];"
                 : "=r"(r[0]), "=r"(r[1]), "=r"(r[2]), "=r"(r[3]) : "r"(addr));
}

__device__ __forceinline__ uint32_t smem_u32(const void* p) {
    return (uint32_t)__cvta_generic_to_shared(p);
}

__device__ __forceinline__ void cp_async16(uint32_t dst, const void* src, int src_size) {
    asm volatile("cp.async.ca.shared.global [%0], [%1], 16, %2;"
                 :: "r"(dst), "l"(src), "r"(src_size) : "memory");
}
#define CP_COMMIT() asm volatile("cp.async.commit_group;" ::: "memory")
#define CP_WAIT0()  asm volatile("cp.async.wait_group 0;" ::: "memory")

__device__ __forceinline__ void split2_pack(float x0, float x1, unsigned& hi, unsigned& lo) {
    __nv_bfloat16 h0 = __float2bfloat16_rn(x0);
    __nv_bfloat16 h1 = __float2bfloat16_rn(x1);
    float r0 = x0 - __bfloat162float(h0);
    float r1 = x1 - __bfloat162float(h1);
    __nv_bfloat16 l0 = __float2bfloat16_rn(r0);
    __nv_bfloat16 l1 = __float2bfloat16_rn(r1);
    hi = (unsigned)__bfloat16_as_ushort(h0) | ((unsigned)__bfloat16_as_ushort(h1) << 16);
    lo = (unsigned)__bfloat16_as_ushort(l0) | ((unsigned)__bfloat16_as_ushort(l1) << 16);
}

// ---------------- bf16 3-pass tensor zgemm (cp.async double-buffer + ldmatrix) ----------
#define ZG_BUF 30720
#define ZG_SMEM (2 * ZG_BUF)
__global__ __launch_bounds__(256) void zgemm_bf16_kernel(int ksplit)
{
    extern __shared__ char dsm[];
    const uint32_t sbase = smem_u32(dsm);

    const int tid = threadIdx.x;
    const int warp = tid >> 5, lane = tid & 31;
    const int m0 = blockIdx.y * 128;
    const int NCH = KZ / 32;
    const int c0 = (NCH * blockIdx.z) / ksplit;
    const int c1 = (NCH * (blockIdx.z + 1)) / ksplit;

    const int wm = (warp & 3) * 32;
    const int wn = (warp >> 2) * 32;
    const int g = lane >> 2, cc = lane & 3;

    float acc[2][4][4];
#pragma unroll
    for (int mt = 0; mt < 2; mt++)
#pragma unroll
        for (int nt = 0; nt < 4; nt++)
#pragma unroll
            for (int r = 0; r < 4; r++) acc[mt][nt][r] = 0.0f;

    const int RB = 80;

    uint32_t aoff[2];
#pragma unroll
    for (int mt = 0; mt < 2; mt++)
        aoff[mt] = (uint32_t)((wm + mt * 16 + (lane & 15)) * RB + (lane >> 4) * 16);
    uint32_t boff[2];
#pragma unroll
    for (int np = 0; np < 2; np++) {
        int grp = lane >> 3, r = lane & 7;
        int nt = np * 2 + (grp >> 1);
        int c8 = (grp & 1) * 8;
        boff[np] = (uint32_t)((wn + nt * 8 + r) * RB + c8 * 2);
    }

    const int ar0 = tid >> 2, ag0 = tid & 3;
    const int br = tid >> 2, bg = tid & 3;

    auto issue = [&](int ch, int buf) {
        int kk = ch * 32;
        uint32_t b = sbase + buf * ZG_BUF;
#pragma unroll
        for (int it = 0; it < 2; it++) {
            int row = (it == 0) ? ar0 : (ar0 + 64);
            int grow = m0 + row;
            int sz = (grow < NN) ? 16 : 0;
            size_t soff = (size_t)(grow < NN ? grow : 0) * KZ + kk + ag0 * 8;
            cp_async16(b + row * RB + ag0 * 16,          &g_zh[soff], sz);
            cp_async16(b + 10240 + row * RB + ag0 * 16,  &g_zl[soff], sz);
        }
        {
            size_t soff = (size_t)br * KZ + kk + bg * 8;
            cp_async16(b + 20480 + br * RB + bg * 16, &g_vh[soff], 16);
            cp_async16(b + 25600 + br * RB + bg * 16, &g_vl[soff], 16);
        }
    };

    int buf = 0;
    issue(c0, 0);
    CP_COMMIT();

    for (int ch = c0; ch < c1; ch++) {
        CP_WAIT0();
        __syncthreads();
        if (ch + 1 < c1) { issue(ch + 1, buf ^ 1); CP_COMMIT(); }

        const uint32_t ahB = sbase + buf * ZG_BUF;
        const uint32_t alB = ahB + 10240;
        const uint32_t bhB = ahB + 20480;
        const uint32_t blB = ahB + 25600;

#pragma unroll
        for (int ks = 0; ks < 2; ks++) {
            const uint32_t kboff = (uint32_t)(ks * 32);

            unsigned ah[2][4], al[2][4];
#pragma unroll
            for (int mt = 0; mt < 2; mt++) {
                ldsm4(ah[mt], ahB + aoff[mt] + kboff);
                ldsm4(al[mt], alB + aoff[mt] + kboff);
            }
#pragma unroll
            for (int np = 0; np < 2; np++) {
                unsigned bhp[4], blp[4];
                ldsm4(bhp, bhB + boff[np] + kboff);
                ldsm4(blp, blB + boff[np] + kboff);
#pragma unroll
                for (int mt = 0; mt < 2; mt++) {
#pragma unroll
                    for (int j = 0; j < 2; j++) {
                        int nt = np * 2 + j;
                        mma_bf16(acc[mt][nt], ah[mt], &bhp[2 * j]);
                        mma_bf16(acc[mt][nt], ah[mt], &blp[2 * j]);
                        mma_bf16(acc[mt][nt], al[mt], &bhp[2 * j]);
                    }
                }
            }
        }
        __syncthreads();
        buf ^= 1;
    }

#pragma unroll
    for (int mt = 0; mt < 2; mt++) {
#pragma unroll
        for (int nt = 0; nt < 4; nt++) {
            int col = wn + nt * 8 + 2 * cc;
#pragma unroll
            for (int rr = 0; rr < 2; rr++) {
                int row = m0 + wm + mt * 16 + g + rr * 8;
                if (row >= NN) continue;
                atomicAdd(&g_m[(size_t)row * 64 + col],     acc[mt][nt][rr * 2 + 0]);
                atomicAdd(&g_m[(size_t)row * 64 + col + 1], acc[mt][nt][rr * 2 + 1]);
            }
        }
    }
}

// ---------------- fused GRU: gi=m@wih^T, gh=h@whh^T, pointwise -> h (in place) --------
// grid = ceil(NN/32) = 313 blocks, 256 threads. Dynamic smem 112KB:
//   wI [64][192] @0, wH [64][192] @49152B, ms [32][64] @98304B, hs @106496B.
// After the GEMM phase the wI region is reused for the gate buffers.
#define GRU_SMEM (2 * 64 * 192 * 4 + 2 * 32 * 64 * 4)   // 114688
__global__ __launch_bounds__(256) void gru_fused_kernel(
    const float* __restrict__ wih, const float* __restrict__ whh,
    const float* __restrict__ bih, const float* __restrict__ bhh)
{
    extern __shared__ float gsm[];
    float* wI = gsm;                   // [64][192]
    float* wH = gsm + 64 * 192;
    float* ms = gsm + 2 * 64 * 192;    // [32][64]
    float* hs = ms + 32 * 64;

    const int tid = threadIdx.x;
    const int n0 = blockIdx.x * 32;

    // load weights transposed: w[col*64+k] -> wT[k][col]
    for (int i = tid; i < 192 * 64; i += 256) {
        int col = i >> 6, k = i & 63;
        wI[k * 192 + col] = wih[i];
        wH[k * 192 + col] = whh[i];
    }
    for (int i = tid; i < 32 * 64; i += 256) {
        int r = i >> 6, k = i & 63;
        int gr = n0 + r;
        float mv = 0.0f, hv = 0.0f;
        if (gr < NN) { mv = g_m[gr * 64 + k]; hv = g_h[gr * 64 + k]; }
        ms[r * 64 + k] = mv;
        hs[r * 64 + k] = hv;
    }
    __syncthreads();

    const int ng = tid >> 5;   // warp id: 4 nodes each
    const int og = tid & 31;   // 6 cols each
    const int r0 = ng * 4, c0 = og * 6;

    float ai[4][6], ah[4][6];
#pragma unroll
    for (int r = 0; r < 4; r++)
#pragma unroll
        for (int c = 0; c < 6; c++) { ai[r][c] = 0.0f; ah[r][c] = 0.0f; }

    for (int k = 0; k < 64; k++) {
        float a[4], b[4];
#pragma unroll
        for (int r = 0; r < 4; r++) {
            a[r] = ms[(r0 + r) * 64 + k];
            b[r] = hs[(r0 + r) * 64 + k];
        }
        float2 wi0 = *reinterpret_cast<float2*>(&wI[k * 192 + c0]);
        float2 wi1 = *reinterpret_cast<float2*>(&wI[k * 192 + c0 + 2]);
        float2 wi2 = *reinterpret_cast<float2*>(&wI[k * 192 + c0 + 4]);
        float2 wh0 = *reinterpret_cast<float2*>(&wH[k * 192 + c0]);
        float2 wh1 = *reinterpret_cast<float2*>(&wH[k * 192 + c0 + 2]);
        float2 wh2 = *reinterpret_cast<float2*>(&wH[k * 192 + c0 + 4]);
#pragma unroll
        for (int r = 0; r < 4; r++) {
            ai[r][0] = fmaf(a[r], wi0.x, ai[r][0]); ai[r][1] = fmaf(a[r], wi0.y, ai[r][1]);
            ai[r][2] = fmaf(a[r], wi1.x, ai[r][2]); ai[r][3] = fmaf(a[r], wi1.y, ai[r][3]);
            ai[r][4] = fmaf(a[r], wi2.x, ai[r][4]); ai[r][5] = fmaf(a[r], wi2.y, ai[r][5]);
            ah[r][0] = fmaf(b[r], wh0.x, ah[r][0]); ah[r][1] = fmaf(b[r], wh0.y, ah[r][1]);
            ah[r][2] = fmaf(b[r], wh1.x, ah[r][2]); ah[r][3] = fmaf(b[r], wh1.y, ah[r][3]);
            ah[r][4] = fmaf(b[r], wh2.x, ah[r][4]); ah[r][5] = fmaf(b[r], wh2.y, ah[r][5]);
        }
    }
    __syncthreads();   // done reading wI/wH; reuse that region for gates

    float* gi = gsm;               // [32][192]
    float* gh = gsm + 32 * 192;    // [32][192]  (fits exactly in wI's 12288 floats)
#pragma unroll
    for (int r = 0; r < 4; r++)
#pragma unroll
        for (int c = 0; c < 6; c++) {
            gi[(r0 + r) * 192 + c0 + c] = ai[r][c];
            gh[(r0 + r) * 192 + c0 + c] = ah[r][c];
        }
    __syncthreads();

    // pointwise: 32 nodes x 64 units = 2048, 8 per thread
#pragma unroll
    for (int q = 0; q < 8; q++) {
        int idx = tid * 8 + q;
        int r = idx >> 6, c = idx & 63;
        int gr = n0 + r;
        if (gr >= NN) continue;
        float vr = gi[r * 192 + c]       + bih[c]       + gh[r * 192 + c]       + bhh[c];
        float vz = gi[r * 192 + 64 + c]  + bih[64 + c]  + gh[r * 192 + 64 + c]  + bhh[64 + c];
        float gin = gi[r * 192 + 128 + c] + bih[128 + c];
        float ghn = gh[r * 192 + 128 + c] + bhh[128 + c];
        float rr = sigf(vr);
        float zz = sigf(vz);
        float nn2 = tanhf(gin + rr * ghn);
        float hold = hs[r * 64 + c];
        g_h[gr * 64 + c] = (1.0f - zz) * nn2 + zz * hold;
    }
}

// ---------------- generic tiled SGEMM ----------------
template <int BM, int BN, int BK, int TM, int TN, int THREADS, bool RELU>
__global__ __launch_bounds__(THREADS) void sgemm_kernel(
    int a_id, const float* a_ext,
    int b_id, const float* b_ext,
    const float* bias,
    int c_id, float* c_ext,
    int M, int N, int K)
{
    const float* __restrict__ A  = (a_id >= 0) ? g_table[a_id] : a_ext;
    const float* __restrict__ Bw = (b_id >= 0) ? g_table[b_id] : b_ext;
    float* __restrict__ C = (c_id >= 0) ? g_table[c_id] : c_ext;

    __shared__ float As[BK][BM + 4];
    __shared__ float Bs[BK][BN + 4];

    const int tid = threadIdx.x;
    const int m0 = blockIdx.y * BM;
    const int n0 = blockIdx.x * BN;
    const int NTX = BN / TN;
    const int tx = tid % NTX;
    const int ty = tid / NTX;

    float acc[TM][TN];
#pragma unroll
    for (int i = 0; i < TM; i++)
#pragma unroll
        for (int j = 0; j < TN; j++) acc[i][j] = 0.0f;

    for (int kk = 0; kk < K; kk += BK) {
#pragma unroll
        for (int idx = tid; idx < BM * BK; idx += THREADS) {
            int mm = idx / BK, k = idx % BK;
            int row = m0 + mm, col = kk + k;
            As[k][mm] = (row < M && col < K) ? A[(size_t)row * K + col] : 0.0f;
        }
#pragma unroll
        for (int idx = tid; idx < BN * BK; idx += THREADS) {
            int nn2 = idx / BK, k = idx % BK;
            int row = n0 + nn2, col = kk + k;
            Bs[k][nn2] = (row < N && col < K) ? Bw[(size_t)row * K + col] : 0.0f;
        }
        __syncthreads();

#pragma unroll
        for (int k = 0; k < BK; k++) {
            float a[TM], b[TN];
#pragma unroll
            for (int i = 0; i < TM; i++) a[i] = As[k][ty * TM + i];
#pragma unroll
            for (int j = 0; j < TN; j++) b[j] = Bs[k][tx * TN + j];
#pragma unroll
            for (int i = 0; i < TM; i++)
#pragma unroll
                for (int j = 0; j < TN; j++) acc[i][j] = fmaf(a[i], b[j], acc[i][j]);
        }
        __syncthreads();
    }

#pragma unroll
    for (int i = 0; i < TM; i++) {
        int row = m0 + ty * TM + i;
        if (row >= M) continue;
#pragma unroll
        for (int j = 0; j < TN; j++) {
            int col = n0 + tx * TN + j;
            if (col >= N) continue;
            float v = acc[i][j] + (bias ? bias[col] : 0.0f);
            if (RELU) v = fmaxf(v, 0.0f);
            C[(size_t)row * N + col] = v;
        }
    }
}

// ---------------- launch 1: table + hist zero + seg init ----------------
__global__ void init_misc_kernel() {
    int i = blockIdx.x * blockDim.x + threadIdx.x;
    if (i == 0) {
        g_table[ID_E1] = g_e1;
        g_table[ID_H] = g_h;   g_table[ID_M] = g_m;
        g_table[ID_HX] = g_hx; g_table[ID_H2] = g_h2;
        g_table[ID_QSTAR] = g_qstar;
        g_table[ID_T2A] = g_t2a;
    }
    if (i < NN) { g_cnt[i] = 0; g_cur[i] = 0; }
    if (i < BG) { g_gs[i] = NN; g_ge[i] = 0; }
}

// ---------------- launch 2: hist + seg_mark ----------------
__global__ void hist_seg_kernel(const int* __restrict__ dst, const int* __restrict__ batch) {
    int i = blockIdx.x * blockDim.x + threadIdx.x;
    if (i < NE) {
        int d = dst[i];
        if ((unsigned)d < NN) atomicAdd(&g_cnt[d], 1);
    }
    if (i < NN) {
        int b = batch[i];
        if ((unsigned)b < BG) {
            atomicMin(&g_gs[b], i);
            atomicMax(&g_ge[b], i + 1);
        }
    }
}

// ---------------- launch 3: scan ----------------
__global__ void scan_kernel() {
    __shared__ int sh[1024];
    __shared__ int carry;
    int tid = threadIdx.x;
    if (tid == 0) carry = 0;
    __syncthreads();
    for (int base = 0; base < NN; base += 1024) {
        int i = base + tid;
        int v = (i < NN) ? g_cnt[i] : 0;
        sh[tid] = v;
        __syncthreads();
        for (int off = 1; off < 1024; off <<= 1) {
            int t = (tid >= off) ? sh[tid - off] : 0;
            __syncthreads();
            sh[tid] += t;
            __syncthreads();
        }
        int c0 = carry;
        int myoff = c0 + sh[tid] - v;
        __syncthreads();
        if (tid == 1023) carry = c0 + sh[1023];
        __syncthreads();
        if (i < NN) g_offs[i] = myoff;
    }
    if (tid == 0) g_offs[NN] = carry;
}

// ---------------- launch 4: MEGA (scatter | init_h | prep_vcat | prep_lstm | edge MLP) --
#define NB_SCAT  ((NE + 255) / 256)
#define NB_INITH ((NN * HD + 255) / 256)
#define NB_PV    ((HD * KZ + 255) / 256)
#define NB_PL    ((384*512 + 256*512 + 1024 + 255) / 256)
#define NB_EMLP  ((NE + 63) / 64)
#define MEGA_BLOCKS (NB_SCAT + NB_INITH + NB_PV + NB_PL + NB_EMLP)

__global__ __launch_bounds__(256) void mega_kernel(
    const int* __restrict__ dst, const float* __restrict__ x,
    const float* __restrict__ w1c, const float* __restrict__ b1c,
    const float* __restrict__ wih0, const float* __restrict__ whh0,
    const float* __restrict__ bih0, const float* __restrict__ bhh0,
    const float* __restrict__ wih1, const float* __restrict__ whh1,
    const float* __restrict__ bih1, const float* __restrict__ bhh1,
    const float* __restrict__ ea,
    const float* __restrict__ w1a, const float* __restrict__ b1a,
    const float* __restrict__ w1b, const float* __restrict__ b1b)
{
    __shared__ float wa_s[NEF][64];
    __shared__ float ba_s[64], bb_s[64];
    __shared__ float wbT[64][68];
    __shared__ float s1[64][65];
    __shared__ float ea_s[64][5];

    int bid = blockIdx.x;
    int tid = threadIdx.x;

    if (bid < NB_SCAT) {
        int e = bid * 256 + tid;
        if (e < NE) {
            int d = dst[e];
            if ((unsigned)d < NN) {
                int p = g_offs[d] + atomicAdd(&g_cur[d], 1);
                g_eord[p] = e;
            }
        }
        return;
    }
    bid -= NB_SCAT;
    if (bid < NB_INITH) {
        int idx = bid * 256 + tid;
        if (idx < NN * HD) {
            int n = idx / HD, c = idx % HD;
            g_h[idx] = (c < NNF) ? x[n * NNF + c] : 0.0f;
        }
        return;
    }
    bid -= NB_INITH;
    if (bid < NB_PV) {
        int idx = bid * 256 + tid;
        if (idx < HD * KZ) {
            int o = idx / KZ, c = idx % KZ;
            float v;
            if (c < 4096) {
                int i = c >> 6, k = c & 63;
                v = w1c[(i * 64 + o) * 64 + k];
            } else {
                v = b1c[(c - 4096) * 64 + o];
            }
            __nv_bfloat16 hb = __float2bfloat16_rn(v);
            g_vh[idx] = hb;
            g_vl[idx] = __float2bfloat16_rn(v - __bfloat162float(hb));
        }
        return;
    }
    bid -= NB_PV;
    if (bid < NB_PL) {
        int i = bid * 256 + tid;
        const int n0 = 384 * 512, n1 = 256 * 512;
        if (i < n0) {
            int k = i / 512, j = i % 512;
            g_wcat0T[i] = (k < 256) ? wih0[j * 256 + k] : whh0[j * 128 + (k - 256)];
        } else if (i < n0 + n1) {
            int q = i - n0; int k = q / 512, j = q % 512;
            g_wcat1T[q] = (k < 128) ? wih1[j * 128 + k] : whh1[j * 128 + (k - 128)];
        } else if (i < n0 + n1 + 512) {
            int j = i - n0 - n1; g_bs0[j] = bih0[j] + bhh0[j];
        } else if (i < n0 + n1 + 1024) {
            int j = i - n0 - n1 - 512; g_bs1[j] = bih1[j] + bhh1[j];
        }
        return;
    }
    bid -= NB_PL;
    // ---- edge MLP: 64 edges per block, 4 edges x 4 outputs per thread ----
    {
        int eb = bid * 64;
        for (int i = tid; i < 64 * NEF; i += 256) { int k = i >> 2, f = i & 3; wa_s[f][k] = w1a[i]; }
        if (tid < 64) { ba_s[tid] = b1a[tid]; bb_s[tid] = b1b[tid]; }
        for (int i = tid; i < 64 * 64; i += 256) { int k = i >> 6, j = i & 63; wbT[j][k] = w1b[i]; }
        for (int i = tid; i < 64 * NEF; i += 256) {
            int e = i >> 2, f = i & 3;
            ea_s[e][f] = (eb + e < NE) ? ea[(size_t)(eb + e) * NEF + f] : 0.0f;
        }
        __syncthreads();

        {
            int e = tid & 63, jg = tid >> 6;
            float a0 = ea_s[e][0], a1 = ea_s[e][1], a2 = ea_s[e][2], a3 = ea_s[e][3];
#pragma unroll
            for (int ji = 0; ji < 16; ji++) {
                int j = jg * 16 + ji;
                float v = ba_s[j];
                v = fmaf(a0, wa_s[0][j], v);
                v = fmaf(a1, wa_s[1][j], v);
                v = fmaf(a2, wa_s[2][j], v);
                v = fmaf(a3, wa_s[3][j], v);
                s1[e][j] = fmaxf(v, 0.0f);
            }
        }
        __syncthreads();

        {
            int e0 = (tid >> 4) * 4;      // 16 groups of 4 edges
            int o0 = (tid & 15) * 4;      // 16 output groups of 4
            float acc[4][4];
#pragma unroll
            for (int r = 0; r < 4; r++)
#pragma unroll
                for (int c = 0; c < 4; c++) acc[r][c] = bb_s[o0 + c];
#pragma unroll 8
            for (int j = 0; j < 64; j++) {
                float4 w = *reinterpret_cast<float4*>(&wbT[j][o0]);
                float s[4];
#pragma unroll
                for (int r = 0; r < 4; r++) s[r] = s1[e0 + r][j];
#pragma unroll
                for (int r = 0; r < 4; r++) {
                    acc[r][0] = fmaf(s[r], w.x, acc[r][0]);
                    acc[r][1] = fmaf(s[r], w.y, acc[r][1]);
                    acc[r][2] = fmaf(s[r], w.z, acc[r][2]);
                    acc[r][3] = fmaf(s[r], w.w, acc[r][3]);
                }
            }
#pragma unroll
            for (int r = 0; r < 4; r++) {
                int e = eb + e0 + r;
                if (e < NE) {
                    float4 v = make_float4(fmaxf(acc[r][0], 0.f), fmaxf(acc[r][1], 0.f),
                                           fmaxf(acc[r][2], 0.f), fmaxf(acc[r][3], 0.f));
                    *reinterpret_cast<float4*>(&g_e1[(size_t)e * 64 + o0]) = v;
                }
            }
        }
    }
}

// ---------------- Z accumulate (zeroes m row; writes pre-split bf16 hi/lo) ----------------
__global__ __launch_bounds__(256) void zacc_kernel(const int* __restrict__ src) {
    __shared__ float sh[4][64];
    __shared__ float se[4][64];
    int d = blockIdx.x;
    int beg = g_offs[d], end = g_offs[d + 1];
    int tid = threadIdx.x;

    if (tid < 64) g_m[d * 64 + tid] = 0.0f;

    int i0 = (tid >> 4) << 2;
    int k0 = (tid & 15) << 2;
    float acc[4][4];
#pragma unroll
    for (int r = 0; r < 4; r++)
#pragma unroll
        for (int c = 0; c < 4; c++) acc[r][c] = 0.0f;
    float hs = 0.0f;

    int j = tid >> 6, l = tid & 63;
    for (int p = beg; p < end; p += 4) {
        int nv = end - p;
        if (j < nv) {
            int e = g_eord[p + j];
            int s = src[e];
            sh[j][l] = ((unsigned)s < NN) ? g_h[s * 64 + l] : 0.0f;
            se[j][l] = g_e1[e * 64 + l];
        } else { sh[j][l] = 0.0f; se[j][l] = 0.0f; }
        __syncthreads();
#pragma unroll
        for (int j2 = 0; j2 < 4; j2++) {
            float4 hv = *reinterpret_cast<float4*>(&sh[j2][i0]);
            float4 ev = *reinterpret_cast<float4*>(&se[j2][k0]);
            acc[0][0] = fmaf(hv.x, ev.x, acc[0][0]); acc[0][1] = fmaf(hv.x, ev.y, acc[0][1]);
            acc[0][2] = fmaf(hv.x, ev.z, acc[0][2]); acc[0][3] = fmaf(hv.x, ev.w, acc[0][3]);
            acc[1][0] = fmaf(hv.y, ev.x, acc[1][0]); acc[1][1] = fmaf(hv.y, ev.y, acc[1][1]);
            acc[1][2] = fmaf(hv.y, ev.z, acc[1][2]); acc[1][3] = fmaf(hv.y, ev.w, acc[1][3]);
            acc[2][0] = fmaf(hv.z, ev.x, acc[2][0]); acc[2][1] = fmaf(hv.z, ev.y, acc[2][1]);
            acc[2][2] = fmaf(hv.z, ev.z, acc[2][2]); acc[2][3] = fmaf(hv.z, ev.w, acc[2][3]);
            acc[3][0] = fmaf(hv.w, ev.x, acc[3][0]); acc[3][1] = fmaf(hv.w, ev.y, acc[3][1]);
            acc[3][2] = fmaf(hv.w, ev.z, acc[3][2]); acc[3][3] = fmaf(hv.w, ev.w, acc[3][3]);
        }
        if (tid < 64) hs += sh[0][tid] + sh[1][tid] + sh[2][tid] + sh[3][tid];
        __syncthreads();
    }

    size_t rowbase = (size_t)d * KZ;
#pragma unroll
    for (int r = 0; r < 4; r++) {
        unsigned h0, l0, h1, l1;
        split2_pack(acc[r][0], acc[r][1], h0, l0);
        split2_pack(acc[r][2], acc[r][3], h1, l1);
        size_t off = rowbase + (size_t)(i0 + r) * 64 + k0;
        *reinterpret_cast<unsigned*>(&g_zh[off])     = h0;
        *reinterpret_cast<unsigned*>(&g_zh[off + 2]) = h1;
        *reinterpret_cast<unsigned*>(&g_zl[off])     = l0;
        *reinterpret_cast<unsigned*>(&g_zl[off + 2]) = l1;
    }
    if (tid < 64) {
        __nv_bfloat16 hb = __float2bfloat16_rn(hs);
        g_zh[rowbase + 4096 + tid] = hb;
        g_zl[rowbase + 4096 + tid] = __float2bfloat16_rn(hs - __bfloat162float(hb));
    }
}

__global__ void concat_hx_kernel(const float* __restrict__ x)
{
    int idx = blockIdx.x * blockDim.x + threadIdx.x;
    const int W = HD + NNF;
    if (idx >= NN * W) return;
    int n = idx / W, c = idx % W;
    g_hx[idx] = (c < HD) ? g_h[n * HD + c] : x[n * NNF + (c - HD)];
}

// ---------------- fused Set2Set LSTM step ----------------
__global__ __launch_bounds__(256) void lstm_step_kernel(int mode)
{
    __shared__ float sa[4][384];
    __shared__ float sg[4][512];

    const int K = mode ? 256 : 384;
    const float* __restrict__ WT = mode ? g_wcat1T : g_wcat0T;
    const float* __restrict__ bs = mode ? g_bs1 : g_bs0;
    float* __restrict__ hS = mode ? g_h1 : g_h0;
    float* __restrict__ cS = mode ? g_c1 : g_c0;

    const int tid = threadIdx.x;
    const int gb0 = blockIdx.x * 4;

    for (int idx = tid; idx < 4 * K; idx += 256) {
        int r = idx / K, c = idx % K;
        int gb = gb0 + r;
        float v;
        if (mode == 0) v = (c < 256) ? g_qstar[gb * 256 + c] : g_h0[gb * 128 + (c - 256)];
        else           v = (c < 128) ? g_h0[gb * 128 + c]    : g_h1[gb * 128 + (c - 128)];
        sa[r][c] = v;
    }
    __syncthreads();

    const int col0 = tid * 2;
    float acc[4][2];
#pragma unroll
    for (int r = 0; r < 4; r++) { acc[r][0] = 0.0f; acc[r][1] = 0.0f; }

    for (int k = 0; k < K; k += 4) {
        float a[4][4];
#pragma unroll
        for (int r = 0; r < 4; r++) {
            float4 av = *reinterpret_cast<float4*>(&sa[r][k]);
            a[r][0] = av.x; a[r][1] = av.y; a[r][2] = av.z; a[r][3] = av.w;
        }
#pragma unroll
        for (int k2 = 0; k2 < 4; k2++) {
            float2 b = *reinterpret_cast<const float2*>(&WT[(size_t)(k + k2) * 512 + col0]);
#pragma unroll
            for (int r = 0; r < 4; r++) {
                acc[r][0] = fmaf(a[r][k2], b.x, acc[r][0]);
                acc[r][1] = fmaf(a[r][k2], b.y, acc[r][1]);
            }
        }
    }

    float b0 = bs[col0], b1 = bs[col0 + 1];
#pragma unroll
    for (int r = 0; r < 4; r++) {
        sg[r][col0]     = acc[r][0] + b0;
        sg[r][col0 + 1] = acc[r][1] + b1;
    }
    __syncthreads();

#pragma unroll
    for (int q = 0; q < 2; q++) {
        int idx = tid * 2 + q;
        int r = idx >> 7, d = idx & 127;
        int gb = gb0 + r;
        float gi = sg[r][d];
        float gf = sg[r][128 + d];
        float gg = sg[r][256 + d];
        float go = sg[r][384 + d];
        float cold = cS[gb * 128 + d];
        float cn = sigf(gf) * cold + sigf(gi) * tanhf(gg);
        cS[gb * 128 + d] = cn;
        hS[gb * 128 + d] = sigf(go) * tanhf(cn);
    }
}

// ---------------- fused attention ----------------
__global__ void attn_fused_kernel()
{
    __shared__ float q[128];
    __shared__ float red[128];
    int b = blockIdx.x;
    int tid = threadIdx.x;
    int s = g_gs[b], e = g_ge[b];

    q[tid] = g_h1[b * 128 + tid];
    __syncthreads();

    int warp = tid >> 5, lane = tid & 31;
    for (int n = s + warp; n < e; n += 4) {
        const float* hr = &g_h2[(size_t)n * 128];
        float sum = hr[lane] * q[lane] + hr[lane + 32] * q[lane + 32]
                  + hr[lane + 64] * q[lane + 64] + hr[lane + 96] * q[lane + 96];
#pragma unroll
        for (int o = 16; o > 0; o >>= 1) sum += __shfl_xor_sync(0xffffffffu, sum, o);
        if (lane == 0) g_eatt[n] = sum;
    }
    __syncthreads();

    float mx = -1e30f;
    for (int n = s + tid; n < e; n += 128) mx = fmaxf(mx, g_eatt[n]);
    red[tid] = mx;
    __syncthreads();
    for (int o = 64; o > 0; o >>= 1) {
        if (tid < o) red[tid] = fmaxf(red[tid], red[tid + o]);
        __syncthreads();
    }
    float m = red[0];

    float rd = 0.0f, den = 0.0f;
    for (int n = s; n < e; n++) {
        float a = expf(g_eatt[n] - m);
        den += a;
        rd = fmaf(a, g_h2[(size_t)n * IC + tid], rd);
    }
    g_qstar[b * 256 + 128 + tid] = (den > 0.0f) ? (rd / den) : 0.0f;
    g_qstar[b * 256 + tid] = q[tid];
}

__global__ void zero_s2s_kernel() {
    int i = blockIdx.x * blockDim.x + threadIdx.x;
    if (i < BG * 256) g_qstar[i] = 0.0f;
    if (i < BG * IC) { g_h0[i] = 0.0f; g_c0[i] = 0.0f; g_h1[i] = 0.0f; g_c1[i] = 0.0f; }
}

// ---------------- host orchestration ----------------
extern "C" void kernel_launch(void* const* d_in, const int* in_sizes, int n_in,
                              void* d_out, int out_size)
{
    const float *x = 0, *ea = 0, *w1a = 0, *b1a = 0, *w1b = 0, *b1b = 0, *w1c = 0, *b1c = 0;
    const float *gwih = 0, *gwhh = 0, *gbih = 0, *gbhh = 0, *linw = 0, *linb = 0;
    const float *lwih0 = 0, *lwhh0 = 0, *lbih0 = 0, *lbhh0 = 0;
    const float *lwih1 = 0, *lwhh1 = 0, *lbih1 = 0, *lbhh1 = 0;
    const float *w2a = 0, *b2a = 0, *w2b = 0, *b2b = 0;
    const int *eidx = 0, *batch = 0;

    int c64 = 0, c4096 = 0, c12288 = 0, c192 = 0, c131072 = 0, c65536 = 0, c512 = 0;
    for (int i = 0; i < n_in; i++) {
        const void* p = d_in[i];
        int s = in_sizes[i];
        if      (s == 110000) x = (const float*)p;
        else if (s == 200000) ea = (const float*)p;
        else if (s == 100000) eidx = (const int*)p;
        else if (s == 10000)  batch = (const int*)p;
        else if (s == 1)      { }
        else if (s == 256)    w1a = (const float*)p;
        else if (s == 64)     { if (c64++ == 0) b1a = (const float*)p; else b1b = (const float*)p; }
        else if (s == 4096)   { if (c4096++ == 0) w1b = (const float*)p; else b1c = (const float*)p; }
        else if (s == 262144) w1c = (const float*)p;
        else if (s == 12288)  { if (c12288++ == 0) gwih = (const float*)p; else gwhh = (const float*)p; }
        else if (s == 192)    { if (c192++ == 0) gbih = (const float*)p; else gbhh = (const float*)p; }
        else if (s == 9600)   linw = (const float*)p;
        else if (s == 128)    linb = (const float*)p;
        else if (s == 131072) { if (c131072++ == 0) lwih0 = (const float*)p; else w2a = (const float*)p; }
        else if (s == 65536)  { int k = c65536++; if (k == 0) lwhh0 = (const float*)p;
                                else if (k == 1) lwih1 = (const float*)p; else lwhh1 = (const float*)p; }
        else if (s == 512)    { int k = c512++;
                                if (k == 0) lbih0 = (const float*)p;
                                else if (k == 1) lbhh0 = (const float*)p;
                                else if (k == 2) lbih1 = (const float*)p;
                                else if (k == 3) lbhh1 = (const float*)p;
                                else b2a = (const float*)p; }
        else if (s == 6144)   w2b = (const float*)p;
        else if (s == 12)     b2b = (const float*)p;
    }
    float* out = (float*)d_out;
    const int* src = eidx;
    const int* dst = eidx + NE;

    const int MB128 = (NN + 127) / 128;   // 79

    cudaFuncSetAttribute(zgemm_bf16_kernel, cudaFuncAttributeMaxDynamicSharedMemorySize, ZG_SMEM);
    cudaFuncSetAttribute(gru_fused_kernel, cudaFuncAttributeMaxDynamicSharedMemorySize, GRU_SMEM);

    // packed prologue
    init_misc_kernel<<<(NN + 255) / 256, 256>>>();
    hist_seg_kernel<<<(NE + 255) / 256, 256>>>(dst, batch);
    scan_kernel<<<1, 1024>>>();
    mega_kernel<<<MEGA_BLOCKS, 256>>>(dst, x, w1c, b1c,
                                      lwih0, lwhh0, lbih0, lbhh0,
                                      lwih1, lwhh1, lbih1, lbhh1,
                                      ea, w1a, b1a, w1b, b1b);

    // T message-passing steps
    for (int t = 0; t < 3; t++) {
        zacc_kernel<<<NN, 256>>>(src);
        {
            dim3 grid(1, MB128, 4);
            zgemm_bf16_kernel<<<grid, 256, ZG_SMEM>>>(4);
        }
        gru_fused_kernel<<<(NN + 31) / 32, 256, GRU_SMEM>>>(gwih, gwhh, gbih, gbhh);
    }

    // lin: h2 = [h|x] @ lin_w^T + lin_b  (K=75)
    concat_hx_kernel<<<(NN * (HD + NNF) + 255) / 256, 256>>>(x);
    {
        dim3 grid((IC + 63) / 64, (NN + 63) / 64);
        sgemm_kernel<64, 64, 16, 4, 4, 256, false><<<grid, 256>>>(
            ID_HX, nullptr, -1, linw, linb, ID_H2, nullptr, NN, IC, HD + NNF);
    }

    // Set2Set (fused)
    zero_s2s_kernel<<<(BG * 256 + 255) / 256, 256>>>();
    for (int ms = 0; ms < 3; ms++) {
        lstm_step_kernel<<<BG / 4, 256>>>(0);
        lstm_step_kernel<<<BG / 4, 256>>>(1);
        attn_fused_kernel<<<BG, 128>>>();
    }

    // output MLP
    {
        dim3 grid1((512 + 63) / 64, (BG + 31) / 32);
        sgemm_kernel<32, 64, 16, 2, 4, 256, true><<<grid1, 256>>>(
            ID_QSTAR, nullptr, -1, w2a, b2a, ID_T2A, nullptr, BG, 512, 256);
        dim3 grid2(1, (BG + 31) / 32);
        sgemm_kernel<32, 64, 16, 2, 4, 256, false><<<grid2, 256>>>(
            ID_T2A, nullptr, -1, w2b, b2b, -1, out, BG, NTG, 512);
    }
}

// round 17
// speedup vs baseline: 1.0961x; 1.0961x over previous
#include <cuda_runtime.h>
#include <cuda_bf16.h>
#include <math.h>
#include <stdint.h>

#define NN  10000   // nodes
#define NE  50000   // edges
#define HD  64      // hidden
#define BG  256     // batch graphs
#define NEF 4
#define NNF 11
#define NTG 12      // targets
#define IC  128     // 2H
#define KZ  4160    // 64*65 : Zcat columns (64i x 64k + 64 hsum)

// ---------------- scratch (static device globals; no allocation) ----------------
__device__ float g_e1[NE * HD];
__device__ __nv_bfloat16 g_zh[(size_t)NN * KZ];        // 83 MB (Z hi)
__device__ __nv_bfloat16 g_zl[(size_t)NN * KZ];        // 83 MB (Z lo)
__device__ __nv_bfloat16 g_vh[HD * KZ];
__device__ __nv_bfloat16 g_vl[HD * KZ];
__device__ float g_h[NN * HD];
__device__ float g_m[NN * HD];
__device__ float g_gi[NN * 3 * HD];
__device__ float g_gh[NN * 3 * HD];
__device__ float g_hx[NN * (HD + NNF)];
__device__ float g_h2[NN * IC];
__device__ float g_eatt[NN];
__device__ float g_qstar[BG * 2 * IC];
__device__ float g_h0[BG * IC];
__device__ float g_c0[BG * IC];
__device__ float g_h1[BG * IC];
__device__ float g_c1[BG * IC];
__device__ float g_wcat0T[384 * 512];   // transposed [K][512]
__device__ float g_wcat1T[256 * 512];
__device__ float g_bs0[512];
__device__ float g_bs1[512];
__device__ float g_t2a[BG * 512];
__device__ int   g_gs[BG];
__device__ int   g_ge[BG];
// edge sort-by-dst
__device__ int   g_cnt[NN];
__device__ int   g_cur[NN];
__device__ int   g_offs[NN + 1];
__device__ int   g_eord[NE];

#define ID_E1     0
#define ID_H      1
#define ID_M      2
#define ID_GI     3
#define ID_GH     4
#define ID_HX     5
#define ID_H2     6
#define ID_QSTAR  7
#define ID_T2A    8
#define N_IDS     9

__device__ float* g_table[N_IDS];

__device__ __forceinline__ float sigf(float x) { return 1.0f / (1.0f + expf(-x)); }

// ---------------- bf16 mma / ldmatrix / cp.async helpers ----------------
__device__ __forceinline__ void mma_bf16(float* d, const unsigned* a, const unsigned* b) {
    asm volatile(
        "mma.sync.aligned.m16n8k16.row.col.f32.bf16.bf16.f32 "
        "{%0,%1,%2,%3}, {%4,%5,%6,%7}, {%8,%9}, {%0,%1,%2,%3};\n"
        : "+f"(d[0]), "+f"(d[1]), "+f"(d[2]), "+f"(d[3])
        : "r"(a[0]), "r"(a[1]), "r"(a[2]), "r"(a[3]), "r"(b[0]), "r"(b[1]));
}

__device__ __forceinline__ void ldsm4(unsigned* r, uint32_t addr) {
    asm volatile("ldmatrix.sync.aligned.m8n8.x4.shared.b16 {%0,%1,%2,%3}, [%4];"
                 : "=r"(r[0]), "=r"(r[1]), "=r"(r[2]), "=r"(r[3]) : "r"(addr));
}

__device__ __forceinline__ uint32_t smem_u32(const void* p) {
    return (uint32_t)__cvta_generic_to_shared(p);
}

__device__ __forceinline__ void cp_async16(uint32_t dst, const void* src, int src_size) {
    asm volatile("cp.async.ca.shared.global [%0], [%1], 16, %2;"
                 :: "r"(dst), "l"(src), "r"(src_size) : "memory");
}
#define CP_COMMIT() asm volatile("cp.async.commit_group;" ::: "memory")
#define CP_WAIT0()  asm volatile("cp.async.wait_group 0;" ::: "memory")

__device__ __forceinline__ void split2_pack(float x0, float x1, unsigned& hi, unsigned& lo) {
    __nv_bfloat16 h0 = __float2bfloat16_rn(x0);
    __nv_bfloat16 h1 = __float2bfloat16_rn(x1);
    float r0 = x0 - __bfloat162float(h0);
    float r1 = x1 - __bfloat162float(h1);
    __nv_bfloat16 l0 = __float2bfloat16_rn(r0);
    __nv_bfloat16 l1 = __float2bfloat16_rn(r1);
    hi = (unsigned)__bfloat16_as_ushort(h0) | ((unsigned)__bfloat16_as_ushort(h1) << 16);
    lo = (unsigned)__bfloat16_as_ushort(l0) | ((unsigned)__bfloat16_as_ushort(l1) << 16);
}

// ---------------- bf16 3-pass tensor zgemm (cp.async double-buffer + ldmatrix) ----------
#define ZG_BUF 30720
#define ZG_SMEM (2 * ZG_BUF)
__global__ __launch_bounds__(256) void zgemm_bf16_kernel(int ksplit)
{
    extern __shared__ char dsm[];
    const uint32_t sbase = smem_u32(dsm);

    const int tid = threadIdx.x;
    const int warp = tid >> 5, lane = tid & 31;
    const int m0 = blockIdx.y * 128;
    const int NCH = KZ / 32;
    const int c0 = (NCH * blockIdx.z) / ksplit;
    const int c1 = (NCH * (blockIdx.z + 1)) / ksplit;

    const int wm = (warp & 3) * 32;
    const int wn = (warp >> 2) * 32;
    const int g = lane >> 2, cc = lane & 3;

    float acc[2][4][4];
#pragma unroll
    for (int mt = 0; mt < 2; mt++)
#pragma unroll
        for (int nt = 0; nt < 4; nt++)
#pragma unroll
            for (int r = 0; r < 4; r++) acc[mt][nt][r] = 0.0f;

    const int RB = 80;

    uint32_t aoff[2];
#pragma unroll
    for (int mt = 0; mt < 2; mt++)
        aoff[mt] = (uint32_t)((wm + mt * 16 + (lane & 15)) * RB + (lane >> 4) * 16);
    uint32_t boff[2];
#pragma unroll
    for (int np = 0; np < 2; np++) {
        int grp = lane >> 3, r = lane & 7;
        int nt = np * 2 + (grp >> 1);
        int c8 = (grp & 1) * 8;
        boff[np] = (uint32_t)((wn + nt * 8 + r) * RB + c8 * 2);
    }

    const int ar0 = tid >> 2, ag0 = tid & 3;
    const int br = tid >> 2, bg = tid & 3;

    auto issue = [&](int ch, int buf) {
        int kk = ch * 32;
        uint32_t b = sbase + buf * ZG_BUF;
#pragma unroll
        for (int it = 0; it < 2; it++) {
            int row = (it == 0) ? ar0 : (ar0 + 64);
            int grow = m0 + row;
            int sz = (grow < NN) ? 16 : 0;
            size_t soff = (size_t)(grow < NN ? grow : 0) * KZ + kk + ag0 * 8;
            cp_async16(b + row * RB + ag0 * 16,          &g_zh[soff], sz);
            cp_async16(b + 10240 + row * RB + ag0 * 16,  &g_zl[soff], sz);
        }
        {
            size_t soff = (size_t)br * KZ + kk + bg * 8;
            cp_async16(b + 20480 + br * RB + bg * 16, &g_vh[soff], 16);
            cp_async16(b + 25600 + br * RB + bg * 16, &g_vl[soff], 16);
        }
    };

    int buf = 0;
    issue(c0, 0);
    CP_COMMIT();

    for (int ch = c0; ch < c1; ch++) {
        CP_WAIT0();
        __syncthreads();
        if (ch + 1 < c1) { issue(ch + 1, buf ^ 1); CP_COMMIT(); }

        const uint32_t ahB = sbase + buf * ZG_BUF;
        const uint32_t alB = ahB + 10240;
        const uint32_t bhB = ahB + 20480;
        const uint32_t blB = ahB + 25600;

#pragma unroll
        for (int ks = 0; ks < 2; ks++) {
            const uint32_t kboff = (uint32_t)(ks * 32);

            unsigned ah[2][4], al[2][4];
#pragma unroll
            for (int mt = 0; mt < 2; mt++) {
                ldsm4(ah[mt], ahB + aoff[mt] + kboff);
                ldsm4(al[mt], alB + aoff[mt] + kboff);
            }
#pragma unroll
            for (int np = 0; np < 2; np++) {
                unsigned bhp[4], blp[4];
                ldsm4(bhp, bhB + boff[np] + kboff);
                ldsm4(blp, blB + boff[np] + kboff);
#pragma unroll
                for (int mt = 0; mt < 2; mt++) {
#pragma unroll
                    for (int j = 0; j < 2; j++) {
                        int nt = np * 2 + j;
                        mma_bf16(acc[mt][nt], ah[mt], &bhp[2 * j]);
                        mma_bf16(acc[mt][nt], ah[mt], &blp[2 * j]);
                        mma_bf16(acc[mt][nt], al[mt], &bhp[2 * j]);
                    }
                }
            }
        }
        __syncthreads();
        buf ^= 1;
    }

#pragma unroll
    for (int mt = 0; mt < 2; mt++) {
#pragma unroll
        for (int nt = 0; nt < 4; nt++) {
            int col = wn + nt * 8 + 2 * cc;
#pragma unroll
            for (int rr = 0; rr < 2; rr++) {
                int row = m0 + wm + mt * 16 + g + rr * 8;
                if (row >= NN) continue;
                atomicAdd(&g_m[(size_t)row * 64 + col],     acc[mt][nt][rr * 2 + 0]);
                atomicAdd(&g_m[(size_t)row * 64 + col + 1], acc[mt][nt][rr * 2 + 1]);
            }
        }
    }
}

// ---------------- generic tiled SGEMM ----------------
template <int BM, int BN, int BK, int TM, int TN, int THREADS, bool RELU>
__global__ __launch_bounds__(THREADS) void sgemm_kernel(
    int a_id, const float* a_ext,
    int b_id, const float* b_ext,
    const float* bias,
    int c_id, float* c_ext,
    int M, int N, int K)
{
    const float* __restrict__ A  = (a_id >= 0) ? g_table[a_id] : a_ext;
    const float* __restrict__ Bw = (b_id >= 0) ? g_table[b_id] : b_ext;
    float* __restrict__ C = (c_id >= 0) ? g_table[c_id] : c_ext;

    __shared__ float As[BK][BM + 4];
    __shared__ float Bs[BK][BN + 4];

    const int tid = threadIdx.x;
    const int m0 = blockIdx.y * BM;
    const int n0 = blockIdx.x * BN;
    const int NTX = BN / TN;
    const int tx = tid % NTX;
    const int ty = tid / NTX;

    float acc[TM][TN];
#pragma unroll
    for (int i = 0; i < TM; i++)
#pragma unroll
        for (int j = 0; j < TN; j++) acc[i][j] = 0.0f;

    for (int kk = 0; kk < K; kk += BK) {
#pragma unroll
        for (int idx = tid; idx < BM * BK; idx += THREADS) {
            int mm = idx / BK, k = idx % BK;
            int row = m0 + mm, col = kk + k;
            As[k][mm] = (row < M && col < K) ? A[(size_t)row * K + col] : 0.0f;
        }
#pragma unroll
        for (int idx = tid; idx < BN * BK; idx += THREADS) {
            int nn2 = idx / BK, k = idx % BK;
            int row = n0 + nn2, col = kk + k;
            Bs[k][nn2] = (row < N && col < K) ? Bw[(size_t)row * K + col] : 0.0f;
        }
        __syncthreads();

#pragma unroll
        for (int k = 0; k < BK; k++) {
            float a[TM], b[TN];
#pragma unroll
            for (int i = 0; i < TM; i++) a[i] = As[k][ty * TM + i];
#pragma unroll
            for (int j = 0; j < TN; j++) b[j] = Bs[k][tx * TN + j];
#pragma unroll
            for (int i = 0; i < TM; i++)
#pragma unroll
                for (int j = 0; j < TN; j++) acc[i][j] = fmaf(a[i], b[j], acc[i][j]);
        }
        __syncthreads();
    }

#pragma unroll
    for (int i = 0; i < TM; i++) {
        int row = m0 + ty * TM + i;
        if (row >= M) continue;
#pragma unroll
        for (int j = 0; j < TN; j++) {
            int col = n0 + tx * TN + j;
            if (col >= N) continue;
            float v = acc[i][j] + (bias ? bias[col] : 0.0f);
            if (RELU) v = fmaxf(v, 0.0f);
            C[(size_t)row * N + col] = v;
        }
    }
}

// ---------------- launch 1: table + hist zero + seg init ----------------
__global__ void init_misc_kernel() {
    int i = blockIdx.x * blockDim.x + threadIdx.x;
    if (i == 0) {
        g_table[ID_E1] = g_e1;
        g_table[ID_H] = g_h;   g_table[ID_M] = g_m;
        g_table[ID_GI] = g_gi; g_table[ID_GH] = g_gh;
        g_table[ID_HX] = g_hx; g_table[ID_H2] = g_h2;
        g_table[ID_QSTAR] = g_qstar;
        g_table[ID_T2A] = g_t2a;
    }
    if (i < NN) { g_cnt[i] = 0; g_cur[i] = 0; }
    if (i < BG) { g_gs[i] = NN; g_ge[i] = 0; }
}

// ---------------- launch 2: hist + seg_mark ----------------
__global__ void hist_seg_kernel(const int* __restrict__ dst, const int* __restrict__ batch) {
    int i = blockIdx.x * blockDim.x + threadIdx.x;
    if (i < NE) {
        int d = dst[i];
        if ((unsigned)d < NN) atomicAdd(&g_cnt[d], 1);
    }
    if (i < NN) {
        int b = batch[i];
        if ((unsigned)b < BG) {
            atomicMin(&g_gs[b], i);
            atomicMax(&g_ge[b], i + 1);
        }
    }
}

// ---------------- launch 3: scan ----------------
__global__ void scan_kernel() {
    __shared__ int sh[1024];
    __shared__ int carry;
    int tid = threadIdx.x;
    if (tid == 0) carry = 0;
    __syncthreads();
    for (int base = 0; base < NN; base += 1024) {
        int i = base + tid;
        int v = (i < NN) ? g_cnt[i] : 0;
        sh[tid] = v;
        __syncthreads();
        for (int off = 1; off < 1024; off <<= 1) {
            int t = (tid >= off) ? sh[tid - off] : 0;
            __syncthreads();
            sh[tid] += t;
            __syncthreads();
        }
        int c0 = carry;
        int myoff = c0 + sh[tid] - v;
        __syncthreads();
        if (tid == 1023) carry = c0 + sh[1023];
        __syncthreads();
        if (i < NN) g_offs[i] = myoff;
    }
    if (tid == 0) g_offs[NN] = carry;
}

// ---------------- launch 4: MEGA (scatter | init_h | prep_vcat | prep_lstm | edge MLP) --
#define NB_SCAT  ((NE + 255) / 256)
#define NB_INITH ((NN * HD + 255) / 256)
#define NB_PV    ((HD * KZ + 255) / 256)
#define NB_PL    ((384*512 + 256*512 + 1024 + 255) / 256)
#define NB_EMLP  ((NE + 63) / 64)
#define MEGA_BLOCKS (NB_SCAT + NB_INITH + NB_PV + NB_PL + NB_EMLP)

__global__ __launch_bounds__(256) void mega_kernel(
    const int* __restrict__ dst, const float* __restrict__ x,
    const float* __restrict__ w1c, const float* __restrict__ b1c,
    const float* __restrict__ wih0, const float* __restrict__ whh0,
    const float* __restrict__ bih0, const float* __restrict__ bhh0,
    const float* __restrict__ wih1, const float* __restrict__ whh1,
    const float* __restrict__ bih1, const float* __restrict__ bhh1,
    const float* __restrict__ ea,
    const float* __restrict__ w1a, const float* __restrict__ b1a,
    const float* __restrict__ w1b, const float* __restrict__ b1b)
{
    __shared__ float wa_s[NEF][64];
    __shared__ float ba_s[64], bb_s[64];
    __shared__ float wbT[64][68];
    __shared__ float s1[64][65];
    __shared__ float ea_s[64][5];

    int bid = blockIdx.x;
    int tid = threadIdx.x;

    if (bid < NB_SCAT) {
        int e = bid * 256 + tid;
        if (e < NE) {
            int d = dst[e];
            if ((unsigned)d < NN) {
                int p = g_offs[d] + atomicAdd(&g_cur[d], 1);
                g_eord[p] = e;
            }
        }
        return;
    }
    bid -= NB_SCAT;
    if (bid < NB_INITH) {
        int idx = bid * 256 + tid;
        if (idx < NN * HD) {
            int n = idx / HD, c = idx % HD;
            g_h[idx] = (c < NNF) ? x[n * NNF + c] : 0.0f;
        }
        return;
    }
    bid -= NB_INITH;
    if (bid < NB_PV) {
        int idx = bid * 256 + tid;
        if (idx < HD * KZ) {
            int o = idx / KZ, c = idx % KZ;
            float v;
            if (c < 4096) {
                int i = c >> 6, k = c & 63;
                v = w1c[(i * 64 + o) * 64 + k];
            } else {
                v = b1c[(c - 4096) * 64 + o];
            }
            __nv_bfloat16 hb = __float2bfloat16_rn(v);
            g_vh[idx] = hb;
            g_vl[idx] = __float2bfloat16_rn(v - __bfloat162float(hb));
        }
        return;
    }
    bid -= NB_PV;
    if (bid < NB_PL) {
        int i = bid * 256 + tid;
        const int n0 = 384 * 512, n1 = 256 * 512;
        if (i < n0) {
            int k = i / 512, j = i % 512;
            g_wcat0T[i] = (k < 256) ? wih0[j * 256 + k] : whh0[j * 128 + (k - 256)];
        } else if (i < n0 + n1) {
            int q = i - n0; int k = q / 512, j = q % 512;
            g_wcat1T[q] = (k < 128) ? wih1[j * 128 + k] : whh1[j * 128 + (k - 128)];
        } else if (i < n0 + n1 + 512) {
            int j = i - n0 - n1; g_bs0[j] = bih0[j] + bhh0[j];
        } else if (i < n0 + n1 + 1024) {
            int j = i - n0 - n1 - 512; g_bs1[j] = bih1[j] + bhh1[j];
        }
        return;
    }
    bid -= NB_PL;
    // ---- edge MLP: 64 edges per block, 4 edges x 4 outputs per thread ----
    {
        int eb = bid * 64;
        for (int i = tid; i < 64 * NEF; i += 256) { int k = i >> 2, f = i & 3; wa_s[f][k] = w1a[i]; }
        if (tid < 64) { ba_s[tid] = b1a[tid]; bb_s[tid] = b1b[tid]; }
        for (int i = tid; i < 64 * 64; i += 256) { int k = i >> 6, j = i & 63; wbT[j][k] = w1b[i]; }
        for (int i = tid; i < 64 * NEF; i += 256) {
            int e = i >> 2, f = i & 3;
            ea_s[e][f] = (eb + e < NE) ? ea[(size_t)(eb + e) * NEF + f] : 0.0f;
        }
        __syncthreads();

        {
            int e = tid & 63, jg = tid >> 6;
            float a0 = ea_s[e][0], a1 = ea_s[e][1], a2 = ea_s[e][2], a3 = ea_s[e][3];
#pragma unroll
            for (int ji = 0; ji < 16; ji++) {
                int j = jg * 16 + ji;
                float v = ba_s[j];
                v = fmaf(a0, wa_s[0][j], v);
                v = fmaf(a1, wa_s[1][j], v);
                v = fmaf(a2, wa_s[2][j], v);
                v = fmaf(a3, wa_s[3][j], v);
                s1[e][j] = fmaxf(v, 0.0f);
            }
        }
        __syncthreads();

        {
            int e0 = (tid >> 4) * 4;      // 16 groups of 4 edges
            int o0 = (tid & 15) * 4;      // 16 output groups of 4
            float acc[4][4];
#pragma unroll
            for (int r = 0; r < 4; r++)
#pragma unroll
                for (int c = 0; c < 4; c++) acc[r][c] = bb_s[o0 + c];
#pragma unroll 8
            for (int j = 0; j < 64; j++) {
                float4 w = *reinterpret_cast<float4*>(&wbT[j][o0]);
                float s[4];
#pragma unroll
                for (int r = 0; r < 4; r++) s[r] = s1[e0 + r][j];
#pragma unroll
                for (int r = 0; r < 4; r++) {
                    acc[r][0] = fmaf(s[r], w.x, acc[r][0]);
                    acc[r][1] = fmaf(s[r], w.y, acc[r][1]);
                    acc[r][2] = fmaf(s[r], w.z, acc[r][2]);
                    acc[r][3] = fmaf(s[r], w.w, acc[r][3]);
                }
            }
#pragma unroll
            for (int r = 0; r < 4; r++) {
                int e = eb + e0 + r;
                if (e < NE) {
                    float4 v = make_float4(fmaxf(acc[r][0], 0.f), fmaxf(acc[r][1], 0.f),
                                           fmaxf(acc[r][2], 0.f), fmaxf(acc[r][3], 0.f));
                    *reinterpret_cast<float4*>(&g_e1[(size_t)e * 64 + o0]) = v;
                }
            }
        }
    }
}

// ---------------- Z accumulate (zeroes m row; writes pre-split bf16 hi/lo) ----------------
__global__ __launch_bounds__(256) void zacc_kernel(const int* __restrict__ src) {
    __shared__ float sh[4][64];
    __shared__ float se[4][64];
    int d = blockIdx.x;
    int beg = g_offs[d], end = g_offs[d + 1];
    int tid = threadIdx.x;

    if (tid < 64) g_m[d * 64 + tid] = 0.0f;

    int i0 = (tid >> 4) << 2;
    int k0 = (tid & 15) << 2;
    float acc[4][4];
#pragma unroll
    for (int r = 0; r < 4; r++)
#pragma unroll
        for (int c = 0; c < 4; c++) acc[r][c] = 0.0f;
    float hs = 0.0f;

    int j = tid >> 6, l = tid & 63;
    for (int p = beg; p < end; p += 4) {
        int nv = end - p;
        if (j < nv) {
            int e = g_eord[p + j];
            int s = src[e];
            sh[j][l] = ((unsigned)s < NN) ? g_h[s * 64 + l] : 0.0f;
            se[j][l] = g_e1[e * 64 + l];
        } else { sh[j][l] = 0.0f; se[j][l] = 0.0f; }
        __syncthreads();
#pragma unroll
        for (int j2 = 0; j2 < 4; j2++) {
            float4 hv = *reinterpret_cast<float4*>(&sh[j2][i0]);
            float4 ev = *reinterpret_cast<float4*>(&se[j2][k0]);
            acc[0][0] = fmaf(hv.x, ev.x, acc[0][0]); acc[0][1] = fmaf(hv.x, ev.y, acc[0][1]);
            acc[0][2] = fmaf(hv.x, ev.z, acc[0][2]); acc[0][3] = fmaf(hv.x, ev.w, acc[0][3]);
            acc[1][0] = fmaf(hv.y, ev.x, acc[1][0]); acc[1][1] = fmaf(hv.y, ev.y, acc[1][1]);
            acc[1][2] = fmaf(hv.y, ev.z, acc[1][2]); acc[1][3] = fmaf(hv.y, ev.w, acc[1][3]);
            acc[2][0] = fmaf(hv.z, ev.x, acc[2][0]); acc[2][1] = fmaf(hv.z, ev.y, acc[2][1]);
            acc[2][2] = fmaf(hv.z, ev.z, acc[2][2]); acc[2][3] = fmaf(hv.z, ev.w, acc[2][3]);
            acc[3][0] = fmaf(hv.w, ev.x, acc[3][0]); acc[3][1] = fmaf(hv.w, ev.y, acc[3][1]);
            acc[3][2] = fmaf(hv.w, ev.z, acc[3][2]); acc[3][3] = fmaf(hv.w, ev.w, acc[3][3]);
        }
        if (tid < 64) hs += sh[0][tid] + sh[1][tid] + sh[2][tid] + sh[3][tid];
        __syncthreads();
    }

    size_t rowbase = (size_t)d * KZ;
#pragma unroll
    for (int r = 0; r < 4; r++) {
        unsigned h0, l0, h1, l1;
        split2_pack(acc[r][0], acc[r][1], h0, l0);
        split2_pack(acc[r][2], acc[r][3], h1, l1);
        size_t off = rowbase + (size_t)(i0 + r) * 64 + k0;
        *reinterpret_cast<unsigned*>(&g_zh[off])     = h0;
        *reinterpret_cast<unsigned*>(&g_zh[off + 2]) = h1;
        *reinterpret_cast<unsigned*>(&g_zl[off])     = l0;
        *reinterpret_cast<unsigned*>(&g_zl[off + 2]) = l1;
    }
    if (tid < 64) {
        __nv_bfloat16 hb = __float2bfloat16_rn(hs);
        g_zh[rowbase + 4096 + tid] = hb;
        g_zl[rowbase + 4096 + tid] = __float2bfloat16_rn(hs - __bfloat162float(hb));
    }
}

// ---------------- GRU pointwise ----------------
__global__ void gru_pointwise_kernel()
{
    int idx = blockIdx.x * blockDim.x + threadIdx.x;
    if (idx >= NN * HD) return;
    int n = idx / HD, c = idx % HD;
    const float* gi = g_gi + n * 3 * HD;
    const float* gh = g_gh + n * 3 * HD;
    float r = sigf(gi[c] + gh[c]);
    float z = sigf(gi[HD + c] + gh[HD + c]);
    float nn = tanhf(gi[2 * HD + c] + r * gh[2 * HD + c]);
    float h = g_h[idx];
    g_h[idx] = (1.0f - z) * nn + z * h;
}

__global__ void concat_hx_kernel(const float* __restrict__ x)
{
    int idx = blockIdx.x * blockDim.x + threadIdx.x;
    const int W = HD + NNF;
    if (idx >= NN * W) return;
    int n = idx / W, c = idx % W;
    g_hx[idx] = (c < HD) ? g_h[n * HD + c] : x[n * NNF + (c - HD)];
}

// ---------------- fused Set2Set LSTM step ----------------
__global__ __launch_bounds__(256) void lstm_step_kernel(int mode)
{
    __shared__ float sa[4][384];
    __shared__ float sg[4][512];

    const int K = mode ? 256 : 384;
    const float* __restrict__ WT = mode ? g_wcat1T : g_wcat0T;
    const float* __restrict__ bs = mode ? g_bs1 : g_bs0;
    float* __restrict__ hS = mode ? g_h1 : g_h0;
    float* __restrict__ cS = mode ? g_c1 : g_c0;

    const int tid = threadIdx.x;
    const int gb0 = blockIdx.x * 4;

    for (int idx = tid; idx < 4 * K; idx += 256) {
        int r = idx / K, c = idx % K;
        int gb = gb0 + r;
        float v;
        if (mode == 0) v = (c < 256) ? g_qstar[gb * 256 + c] : g_h0[gb * 128 + (c - 256)];
        else           v = (c < 128) ? g_h0[gb * 128 + c]    : g_h1[gb * 128 + (c - 128)];
        sa[r][c] = v;
    }
    __syncthreads();

    const int col0 = tid * 2;
    float acc[4][2];
#pragma unroll
    for (int r = 0; r < 4; r++) { acc[r][0] = 0.0f; acc[r][1] = 0.0f; }

    for (int k = 0; k < K; k += 4) {
        float a[4][4];
#pragma unroll
        for (int r = 0; r < 4; r++) {
            float4 av = *reinterpret_cast<float4*>(&sa[r][k]);
            a[r][0] = av.x; a[r][1] = av.y; a[r][2] = av.z; a[r][3] = av.w;
        }
#pragma unroll
        for (int k2 = 0; k2 < 4; k2++) {
            float2 b = *reinterpret_cast<const float2*>(&WT[(size_t)(k + k2) * 512 + col0]);
#pragma unroll
            for (int r = 0; r < 4; r++) {
                acc[r][0] = fmaf(a[r][k2], b.x, acc[r][0]);
                acc[r][1] = fmaf(a[r][k2], b.y, acc[r][1]);
            }
        }
    }

    float b0 = bs[col0], b1 = bs[col0 + 1];
#pragma unroll
    for (int r = 0; r < 4; r++) {
        sg[r][col0]     = acc[r][0] + b0;
        sg[r][col0 + 1] = acc[r][1] + b1;
    }
    __syncthreads();

#pragma unroll
    for (int q = 0; q < 2; q++) {
        int idx = tid * 2 + q;
        int r = idx >> 7, d = idx & 127;
        int gb = gb0 + r;
        float gi = sg[r][d];
        float gf = sg[r][128 + d];
        float gg = sg[r][256 + d];
        float go = sg[r][384 + d];
        float cold = cS[gb * 128 + d];
        float cn = sigf(gf) * cold + sigf(gi) * tanhf(gg);
        cS[gb * 128 + d] = cn;
        hS[gb * 128 + d] = sigf(go) * tanhf(cn);
    }
}

// ---------------- fused attention ----------------
__global__ void attn_fused_kernel()
{
    __shared__ float q[128];
    __shared__ float red[128];
    int b = blockIdx.x;
    int tid = threadIdx.x;
    int s = g_gs[b], e = g_ge[b];

    q[tid] = g_h1[b * 128 + tid];
    __syncthreads();

    int warp = tid >> 5, lane = tid & 31;
    for (int n = s + warp; n < e; n += 4) {
        const float* hr = &g_h2[(size_t)n * 128];
        float sum = hr[lane] * q[lane] + hr[lane + 32] * q[lane + 32]
                  + hr[lane + 64] * q[lane + 64] + hr[lane + 96] * q[lane + 96];
#pragma unroll
        for (int o = 16; o > 0; o >>= 1) sum += __shfl_xor_sync(0xffffffffu, sum, o);
        if (lane == 0) g_eatt[n] = sum;
    }
    __syncthreads();

    float mx = -1e30f;
    for (int n = s + tid; n < e; n += 128) mx = fmaxf(mx, g_eatt[n]);
    red[tid] = mx;
    __syncthreads();
    for (int o = 64; o > 0; o >>= 1) {
        if (tid < o) red[tid] = fmaxf(red[tid], red[tid + o]);
        __syncthreads();
    }
    float m = red[0];

    float rd = 0.0f, den = 0.0f;
    for (int n = s; n < e; n++) {
        float a = expf(g_eatt[n] - m);
        den += a;
        rd = fmaf(a, g_h2[(size_t)n * IC + tid], rd);
    }
    g_qstar[b * 256 + 128 + tid] = (den > 0.0f) ? (rd / den) : 0.0f;
    g_qstar[b * 256 + tid] = q[tid];
}

__global__ void zero_s2s_kernel() {
    int i = blockIdx.x * blockDim.x + threadIdx.x;
    if (i < BG * 256) g_qstar[i] = 0.0f;
    if (i < BG * IC) { g_h0[i] = 0.0f; g_c0[i] = 0.0f; g_h1[i] = 0.0f; g_c1[i] = 0.0f; }
}

// ---------------- host orchestration ----------------
extern "C" void kernel_launch(void* const* d_in, const int* in_sizes, int n_in,
                              void* d_out, int out_size)
{
    const float *x = 0, *ea = 0, *w1a = 0, *b1a = 0, *w1b = 0, *b1b = 0, *w1c = 0, *b1c = 0;
    const float *gwih = 0, *gwhh = 0, *gbih = 0, *gbhh = 0, *linw = 0, *linb = 0;
    const float *lwih0 = 0, *lwhh0 = 0, *lbih0 = 0, *lbhh0 = 0;
    const float *lwih1 = 0, *lwhh1 = 0, *lbih1 = 0, *lbhh1 = 0;
    const float *w2a = 0, *b2a = 0, *w2b = 0, *b2b = 0;
    const int *eidx = 0, *batch = 0;

    int c64 = 0, c4096 = 0, c12288 = 0, c192 = 0, c131072 = 0, c65536 = 0, c512 = 0;
    for (int i = 0; i < n_in; i++) {
        const void* p = d_in[i];
        int s = in_sizes[i];
        if      (s == 110000) x = (const float*)p;
        else if (s == 200000) ea = (const float*)p;
        else if (s == 100000) eidx = (const int*)p;
        else if (s == 10000)  batch = (const int*)p;
        else if (s == 1)      { }
        else if (s == 256)    w1a = (const float*)p;
        else if (s == 64)     { if (c64++ == 0) b1a = (const float*)p; else b1b = (const float*)p; }
        else if (s == 4096)   { if (c4096++ == 0) w1b = (const float*)p; else b1c = (const float*)p; }
        else if (s == 262144) w1c = (const float*)p;
        else if (s == 12288)  { if (c12288++ == 0) gwih = (const float*)p; else gwhh = (const float*)p; }
        else if (s == 192)    { if (c192++ == 0) gbih = (const float*)p; else gbhh = (const float*)p; }
        else if (s == 9600)   linw = (const float*)p;
        else if (s == 128)    linb = (const float*)p;
        else if (s == 131072) { if (c131072++ == 0) lwih0 = (const float*)p; else w2a = (const float*)p; }
        else if (s == 65536)  { int k = c65536++; if (k == 0) lwhh0 = (const float*)p;
                                else if (k == 1) lwih1 = (const float*)p; else lwhh1 = (const float*)p; }
        else if (s == 512)    { int k = c512++;
                                if (k == 0) lbih0 = (const float*)p;
                                else if (k == 1) lbhh0 = (const float*)p;
                                else if (k == 2) lbih1 = (const float*)p;
                                else if (k == 3) lbhh1 = (const float*)p;
                                else b2a = (const float*)p; }
        else if (s == 6144)   w2b = (const float*)p;
        else if (s == 12)     b2b = (const float*)p;
    }
    float* out = (float*)d_out;
    const int* src = eidx;
    const int* dst = eidx + NE;

    const int MB128 = (NN + 127) / 128;   // 79

    cudaFuncSetAttribute(zgemm_bf16_kernel, cudaFuncAttributeMaxDynamicSharedMemorySize, ZG_SMEM);

    // packed prologue
    init_misc_kernel<<<(NN + 255) / 256, 256>>>();
    hist_seg_kernel<<<(NE + 255) / 256, 256>>>(dst, batch);
    scan_kernel<<<1, 1024>>>();
    mega_kernel<<<MEGA_BLOCKS, 256>>>(dst, x, w1c, b1c,
                                      lwih0, lwhh0, lbih0, lbhh0,
                                      lwih1, lwhh1, lbih1, lbhh1,
                                      ea, w1a, b1a, w1b, b1b);

    // T message-passing steps
    for (int t = 0; t < 3; t++) {
        zacc_kernel<<<NN, 256>>>(src);
        {
            dim3 grid(1, MB128, 4);
            zgemm_bf16_kernel<<<grid, 256, ZG_SMEM>>>(4);
        }
        {
            dim3 grid((3 * HD + 63) / 64, (NN + 63) / 64);
            sgemm_kernel<64, 64, 16, 4, 4, 256, false><<<grid, 256>>>(
                ID_M, nullptr, -1, gwih, gbih, ID_GI, nullptr, NN, 3 * HD, HD);
            sgemm_kernel<64, 64, 16, 4, 4, 256, false><<<grid, 256>>>(
                ID_H, nullptr, -1, gwhh, gbhh, ID_GH, nullptr, NN, 3 * HD, HD);
        }
        gru_pointwise_kernel<<<(NN * HD + 255) / 256, 256>>>();
    }

    // lin: h2 = [h|x] @ lin_w^T + lin_b  (K=75)
    concat_hx_kernel<<<(NN * (HD + NNF) + 255) / 256, 256>>>(x);
    {
        dim3 grid((IC + 63) / 64, (NN + 63) / 64);
        sgemm_kernel<64, 64, 16, 4, 4, 256, false><<<grid, 256>>>(
            ID_HX, nullptr, -1, linw, linb, ID_H2, nullptr, NN, IC, HD + NNF);
    }

    // Set2Set (fused)
    zero_s2s_kernel<<<(BG * 256 + 255) / 256, 256>>>();
    for (int ms = 0; ms < 3; ms++) {
        lstm_step_kernel<<<BG / 4, 256>>>(0);
        lstm_step_kernel<<<BG / 4, 256>>>(1);
        attn_fused_kernel<<<BG, 128>>>();
    }

    // output MLP
    {
        dim3 grid1((512 + 63) / 64, (BG + 31) / 32);
        sgemm_kernel<32, 64, 16, 2, 4, 256, true><<<grid1, 256>>>(
            ID_QSTAR, nullptr, -1, w2a, b2a, ID_T2A, nullptr, BG, 512, 256);
        dim3 grid2(1, (BG + 31) / 32);
        sgemm_kernel<32, 64, 16, 2, 4, 256, false><<<grid2, 256>>>(
            ID_T2A, nullptr, -1, w2b, b2b, -1, out, BG, NTG, 512);
    }
}